// round 4
// baseline (speedup 1.0000x reference)
#include <cuda_runtime.h>
#include <cstdint>

#define B 16
#define S 4096
#define E 2048
#define WIN 64
#define ROWS (B * S)

#define DOT_BLOCKS      (ROWS / 8)          // 8192, 8 rows (warps) per block
#define DOT_BLK_PER_BAT (DOT_BLOCKS / B)    // 512
#define CHUNKS 16                           // window chunks per batch
#define WPB 256                             // window starts per chunk block
#define NWIN (S - WIN + 1)                  // 4033
#define TOTAL_BLOCKS (DOT_BLOCKS + B * CHUNKS)  // 8448

__device__ float g_scores[ROWS];
__device__ float g_part[B * CHUNKS];
__device__ int   g_cnt_dot[B];   // zero-init; reset by final block each run
__device__ int   g_cnt_win[B];

__global__ __launch_bounds__(256) void fused_kernel(
    const float* __restrict__ x,
    const int*   __restrict__ mask,   // int32 {0,1} or float32 {0.,1.} bit patterns
    const float* __restrict__ W,
    const float* __restrict__ bias,
    float*       __restrict__ out)
{
    const int t = threadIdx.x;

    if (blockIdx.x < DOT_BLOCKS) {
        // ------------------- DOT role: one warp per row -------------------
        const int row  = (blockIdx.x << 3) + (t >> 5);
        const int lane = t & 31;
        const int b    = blockIdx.x / DOT_BLK_PER_BAT;

        const float4* __restrict__ xr = reinterpret_cast<const float4*>(x) + (size_t)row * (E / 4);
        const float4* __restrict__ Wv = reinterpret_cast<const float4*>(W);

        float s0 = 0.f, s1 = 0.f, s2 = 0.f, s3 = 0.f;
        #pragma unroll
        for (int i = 0; i < 16; i += 4) {
            float4 a0 = __ldcs(&xr[lane + (i + 0) * 32]);
            float4 a1 = __ldcs(&xr[lane + (i + 1) * 32]);
            float4 a2 = __ldcs(&xr[lane + (i + 2) * 32]);
            float4 a3 = __ldcs(&xr[lane + (i + 3) * 32]);
            float4 w0 = Wv[lane + (i + 0) * 32];
            float4 w1 = Wv[lane + (i + 1) * 32];
            float4 w2 = Wv[lane + (i + 2) * 32];
            float4 w3 = Wv[lane + (i + 3) * 32];
            s0 += a0.x * w0.x + a0.y * w0.y + a0.z * w0.z + a0.w * w0.w;
            s1 += a1.x * w1.x + a1.y * w1.y + a1.z * w1.z + a1.w * w1.w;
            s2 += a2.x * w2.x + a2.y * w2.y + a2.z * w2.z + a2.w * w2.w;
            s3 += a3.x * w3.x + a3.y * w3.y + a3.z * w3.z + a3.w * w3.w;
        }
        float sum = (s0 + s1) + (s2 + s3);

        #pragma unroll
        for (int o = 16; o > 0; o >>= 1)
            sum += __shfl_xor_sync(0xFFFFFFFFu, sum, o);

        if (lane == 0) {
            float tot = sum + bias[0];
            g_scores[row] = (mask[row] != 0) ? tot : 0.0f;
        }
        __syncthreads();
        if (t == 0) {
            __threadfence();                   // release scores
            atomicAdd(&g_cnt_dot[b], 1);
        }
        return;
    }

    // ------------------- WINDOW role: last 256 blocks -------------------
    const int widx  = blockIdx.x - DOT_BLOCKS;
    const int b     = widx >> 4;          // widx / CHUNKS
    const int chunk = widx & 15;
    const int base  = chunk * WPB;

    // Wait for all dot blocks of this batch
    if (t == 0) {
        while (atomicAdd(&g_cnt_dot[b], 0) < DOT_BLK_PER_BAT)
            __nanosleep(200);
    }
    __syncthreads();
    __threadfence();                          // acquire scores

    __shared__ float sm[WPB + WIN - 1];       // 319
    const float* __restrict__ src = g_scores + (size_t)b * S;
    for (int i = t; i < WPB + WIN - 1; i += 256) {
        int idx = base + i;
        sm[i] = (idx < S) ? src[idx] : 0.0f;
    }
    __syncthreads();

    float best = -3.4e38f;
    if (base + t < NWIN) {
        float acc = 0.0f;
        #pragma unroll
        for (int k = 0; k < WIN; k++) acc += sm[t + k];
        best = acc;
    }
    #pragma unroll
    for (int o = 16; o > 0; o >>= 1)
        best = fmaxf(best, __shfl_xor_sync(0xFFFFFFFFu, best, o));

    __shared__ float pm[8];
    if ((t & 31) == 0) pm[t >> 5] = best;
    __syncthreads();

    if (t == 0) {
        float m = pm[0];
        #pragma unroll
        for (int i = 1; i < 8; i++) m = fmaxf(m, pm[i]);
        g_part[b * CHUNKS + chunk] = m;
        __threadfence();                      // release partial
        int prev = atomicAdd(&g_cnt_win[b], 1);
        if (prev == CHUNKS - 1) {
            __threadfence();                  // acquire partials
            float mm = -3.4e38f;
            #pragma unroll
            for (int c = 0; c < CHUNKS; c++)
                mm = fmaxf(mm, g_part[b * CHUNKS + c]);
            out[b] = mm / (float)WIN;
            // reset counters for next graph replay
            g_cnt_dot[b] = 0;
            g_cnt_win[b] = 0;
        }
    }
}

extern "C" void kernel_launch(void* const* d_in, const int* in_sizes, int n_in,
                              void* d_out, int out_size)
{
    const float* x    = (const float*)d_in[0];
    const int*   mask = (const int*)  d_in[1];
    const float* W    = (const float*)d_in[2];
    const float* bias = (const float*)d_in[3];
    float*       out  = (float*)d_out;

    fused_kernel<<<TOTAL_BLOCKS, 256>>>(x, mask, W, bias, out);
}